// round 7
// baseline (speedup 1.0000x reference)
#include <cuda_runtime.h>
#include <cuda_bf16.h>

// Fixed problem shapes
#define B    8
#define T    16
#define C    64
#define H    56
#define W_   56
#define HW   (H * W_)          // 3136
#define HW4  (HW / 4)          // 784
#define DIM  8
#define POOL 7                 // H/DIM
#define FEAT (DIM * DIM)       // 64
#define DH   64                // dim_head
#define BC   (B * C)           // 512
#define LN_EPS 1e-5f

#define CHUNK_B 2              // batches per pipeline chunk (25.7 MB of x)

// Static device scratch (no allocations allowed)
__device__ float g_pool[BC * T * FEAT];   // (bc, t, 64)  = 2 MB

// Packed f32x2 FMA (Blackwell)
__device__ __forceinline__ unsigned long long ffma2(unsigned long long a,
                                                    unsigned long long b,
                                                    unsigned long long c)
{
    unsigned long long d;
    asm("fma.rn.f32x2 %0, %1, %2, %3;" : "=l"(d) : "l"(a), "l"(b), "l"(c));
    return d;
}

union F4U { float4 f; unsigned long long u[2]; };

// ---------------------------------------------------------------------------
// K1: one CTA per (b,t,c) slice within the chunk. Stage 12.5 KB in smem,
// 7x7 mean-pool -> 64 cells, compile-time reduce offsets.
// ---------------------------------------------------------------------------
__global__ __launch_bounds__(256, 8)
void pool_kernel(const float* __restrict__ x, int slice0)
{
    const int slice = slice0 + blockIdx.x;   // ((b*T + t)*C + c)
    const int c = slice % C;
    const int t = (slice / C) % T;
    const int b = slice / (T * C);
    const int tid = threadIdx.x;

    __shared__ float stage[HW];              // 12544 B

    const float4* xs = reinterpret_cast<const float4*>(x) + (long)slice * HW4;
    float4* st4 = reinterpret_cast<float4*>(stage);
    // 784 = 3*256 + 16
    st4[tid]        = __ldg(&xs[tid]);
    st4[tid + 256]  = __ldg(&xs[tid + 256]);
    st4[tid + 512]  = __ldg(&xs[tid + 512]);
    if (tid < 16) st4[tid + 768] = __ldg(&xs[tid + 768]);
    __syncthreads();

    // 64 cells x 4 subs. sub handles rows {sub, sub+4} (sub==3: one row).
    const int cell = tid >> 2;
    const int sub  = tid & 3;
    const int ci   = cell >> 3;
    const int cj   = cell & 7;

    const float* r0 = stage + (ci * POOL + sub) * W_ + cj * POOL;
    float sum = 0.f;
    #pragma unroll
    for (int jj = 0; jj < POOL; jj++) sum += r0[jj];
    if (sub < 3) {
        #pragma unroll
        for (int jj = 0; jj < POOL; jj++) sum += r0[4 * W_ + jj];
    }
    sum += __shfl_xor_sync(0xffffffffu, sum, 1);
    sum += __shfl_xor_sync(0xffffffffu, sum, 2);
    if (sub == 0)
        g_pool[((b * C + c) * T + t) * FEAT + cell] = sum * (1.f / (POOL * POOL));
}

// ---------------------------------------------------------------------------
// K2 (fused): grid (4, CHUNK_B*C). Each block redundantly computes the 16x16
// attention for its (b,c) from g_pool (cheap prologue), then applies
// out[t] = x[t] + sum_j a[t][j]*x[j] for its 256 float4 positions.
// x reads hit L2 (chunk just streamed by K1). Streaming stores for out.
// ---------------------------------------------------------------------------
__global__ __launch_bounds__(256)
void attn_out_kernel(const float* __restrict__ x,
                     const float* __restrict__ pos,
                     const float* __restrict__ Wqk,
                     const float* __restrict__ gamma,
                     const float* __restrict__ beta,
                     float* __restrict__ out,
                     int bc0)
{
    const int bc  = bc0 + blockIdx.y;
    const int tid = threadIdx.x;

    __shared__ float s[T][FEAT];               // 4 KB
    __shared__ float qk[T][2 * DH];            // 8 KB
    __shared__ float mu[T], rs[T];
    __shared__ unsigned long long a2[T * T];   // packed {w,w}, 2 KB

    // ---- tokens + pos ----
    {
        float* sf = &s[0][0];
        const float* gp = g_pool + bc * (T * FEAT);
        const float* pp = pos    + bc * (T * FEAT);
        for (int i = tid; i < T * FEAT; i += 256) sf[i] = gp[i] + pp[i];
    }
    __syncthreads();

    // ---- LayerNorm ----
    if (tid < T) {
        float m = 0.f, v = 0.f;
        #pragma unroll
        for (int f = 0; f < FEAT; f++) { float val = s[tid][f]; m += val; v += val * val; }
        m *= (1.f / FEAT);
        v = v * (1.f / FEAT) - m * m;
        mu[tid] = m;
        rs[tid] = rsqrtf(v + LN_EPS);
    }
    __syncthreads();
    {
        float* sf = &s[0][0];
        for (int i = tid; i < T * FEAT; i += 256) {
            int t = i >> 6, f = i & 63;
            sf[i] = (sf[i] - mu[t]) * rs[t] * gamma[f] + beta[f];
        }
    }
    __syncthreads();

    // ---- qk = s @ Wqk ----
    for (int i = tid; i < T * 2 * DH; i += 256) {
        const int t = i >> 7;
        const int o = i & 127;
        float acc = 0.f;
        #pragma unroll
        for (int f = 0; f < FEAT; f++) acc += s[t][f] * __ldg(&Wqk[f * (2 * DH) + o]);
        qk[t][o] = acc;
    }
    __syncthreads();

    // ---- dots + softmax -> a2 (packed) ----
    {
        const int i = tid >> 4;
        const int j = tid & 15;
        float d = 0.f;
        #pragma unroll
        for (int k = 0; k < DH; k++) d += qk[i][k] * qk[j][DH + k];
        d *= 0.125f;                           // DH^-0.5

        float mx = d;
        #pragma unroll
        for (int m = 8; m; m >>= 1) mx = fmaxf(mx, __shfl_xor_sync(0xffffffffu, mx, m, 16));
        float e = __expf(d - mx);
        float ss = e;
        #pragma unroll
        for (int m = 8; m; m >>= 1) ss += __shfl_xor_sync(0xffffffffu, ss, m, 16);

        const float w = e / ss;
        unsigned long long wp;
        asm("mov.b64 %0, {%1, %1};" : "=l"(wp) : "f"(w));
        a2[i * T + j] = wp;
    }
    __syncthreads();

    // ---- output pass: one float4 position per thread ----
    const int p = blockIdx.x * 256 + tid;
    if (p >= HW4) return;

    const int b = bc >> 6;
    const int c = bc & 63;

    const float4* xb = reinterpret_cast<const float4*>(x);
    float4*       ob = reinterpret_cast<float4*>(out);

    const int base    = (b * T * C + c) * HW4;   // t = 0
    const int tstride = C * HW4;                 // per-t stride (float4)

    unsigned long long xv[T][2];
    #pragma unroll
    for (int j = 0; j < T; j++) {
        F4U v; v.f = __ldg(&xb[base + j * tstride + p]);   // L2-hot from K1
        xv[j][0] = v.u[0];
        xv[j][1] = v.u[1];
    }

    #pragma unroll
    for (int t = 0; t < T; t++) {
        unsigned long long acc0 = xv[t][0];   // residual
        unsigned long long acc1 = xv[t][1];
        #pragma unroll
        for (int j = 0; j < T; j++) {
            const unsigned long long wp = a2[t * T + j];
            acc0 = ffma2(wp, xv[j][0], acc0);
            acc1 = ffma2(wp, xv[j][1], acc1);
        }
        F4U r; r.u[0] = acc0; r.u[1] = acc1;
        __stcs(&ob[base + t * tstride + p], r.f);
    }
}

// ---------------------------------------------------------------------------
extern "C" void kernel_launch(void* const* d_in, const int* in_sizes, int n_in,
                              void* d_out, int out_size)
{
    const float* x     = (const float*)d_in[0];   // (8,16,64,56,56)
    const float* pos   = (const float*)d_in[1];   // (512,16,64)
    const float* Wqk   = (const float*)d_in[2];   // (64,128)
    const float* gamma = (const float*)d_in[3];   // (64,)
    const float* beta  = (const float*)d_in[4];   // (64,)
    float*       out   = (float*)d_out;

    // Chunked pipeline: keep each 25.7 MB x-chunk L2-resident between its
    // pool pass and its output pass.
    for (int b0 = 0; b0 < B; b0 += CHUNK_B) {
        pool_kernel<<<CHUNK_B * T * C, 256>>>(x, b0 * T * C);
        attn_out_kernel<<<dim3((HW4 + 255) / 256, CHUNK_B * C), 256>>>(
            x, pos, Wqk, gamma, beta, out, b0 * C);
    }
}

// round 9
// speedup vs baseline: 1.5105x; 1.5105x over previous
#include <cuda_runtime.h>
#include <cuda_bf16.h>

// Fixed problem shapes
#define B    8
#define T    16
#define C    64
#define H    56
#define W_   56
#define HW   (H * W_)          // 3136
#define HW4  (HW / 4)          // 784  (float4 units)
#define HW2  (HW / 2)          // 1568 (float2 units)
#define DIM  8
#define POOL 7                 // H/DIM
#define FEAT (DIM * DIM)       // 64
#define DH   64                // dim_head
#define BC   (B * C)           // 512
#define LN_EPS 1e-5f

#define CHUNK_B 4              // batches per pipeline chunk (51.4 MB of x < 126 MB L2)

// Static device scratch (no allocations allowed)
__device__ float              g_pool[BC * T * FEAT];       // 2 MB
__device__ unsigned long long g_attn2[BC * T * T];         // packed {w,w}, 1 MB

// Packed f32x2 ops (Blackwell)
__device__ __forceinline__ unsigned long long ffma2(unsigned long long a,
                                                    unsigned long long b,
                                                    unsigned long long c)
{
    unsigned long long d;
    asm("fma.rn.f32x2 %0, %1, %2, %3;" : "=l"(d) : "l"(a), "l"(b), "l"(c));
    return d;
}
__device__ __forceinline__ unsigned long long fadd2(unsigned long long a,
                                                    unsigned long long b)
{
    unsigned long long d;
    asm("add.rn.f32x2 %0, %1, %2;" : "=l"(d) : "l"(a), "l"(b));
    return d;
}

// ---------------------------------------------------------------------------
// K1: one CTA per (b,t,c) slice within the chunk. Stage 12.5 KB in smem,
// 7x7 mean-pool -> 64 cells, compile-time reduce offsets.
// ---------------------------------------------------------------------------
__global__ __launch_bounds__(256, 8)
void pool_kernel(const float* __restrict__ x, int slice0)
{
    const int slice = slice0 + blockIdx.x;   // ((b*T + t)*C + c)
    const int c = slice % C;
    const int t = (slice / C) % T;
    const int b = slice / (T * C);
    const int tid = threadIdx.x;

    __shared__ float stage[HW];              // 12544 B

    const float4* xs = reinterpret_cast<const float4*>(x) + (long)slice * HW4;
    float4* st4 = reinterpret_cast<float4*>(stage);
    // 784 = 3*256 + 16
    st4[tid]        = xs[tid];
    st4[tid + 256]  = xs[tid + 256];
    st4[tid + 512]  = xs[tid + 512];
    if (tid < 16) st4[tid + 768] = xs[tid + 768];
    __syncthreads();

    // 64 cells x 4 subs. sub handles rows {sub, sub+4} (sub==3: one row).
    const int cell = tid >> 2;
    const int sub  = tid & 3;
    const int ci   = cell >> 3;
    const int cj   = cell & 7;

    const float* r0 = stage + (ci * POOL + sub) * W_ + cj * POOL;
    float sum = 0.f;
    #pragma unroll
    for (int jj = 0; jj < POOL; jj++) sum += r0[jj];
    if (sub < 3) {
        #pragma unroll
        for (int jj = 0; jj < POOL; jj++) sum += r0[4 * W_ + jj];
    }
    sum += __shfl_xor_sync(0xffffffffu, sum, 1);
    sum += __shfl_xor_sync(0xffffffffu, sum, 2);
    if (sub == 0)
        g_pool[((b * C + c) * T + t) * FEAT + cell] = sum * (1.f / (POOL * POOL));
}

// ---------------------------------------------------------------------------
// K2: one CTA per (b,c) in chunk. +pos, LN, QK proj, dots, softmax ->
// packed {w,w} weights in g_attn2. Tiny.
// ---------------------------------------------------------------------------
__global__ __launch_bounds__(256, 4)
void attn_kernel(const float* __restrict__ pos,
                 const float* __restrict__ Wqk,
                 const float* __restrict__ gamma,
                 const float* __restrict__ beta,
                 int bc0)
{
    const int bc  = bc0 + blockIdx.x;
    const int tid = threadIdx.x;

    __shared__ float s[T][FEAT];        // 4 KB
    __shared__ float qk[T][2 * DH];     // 8 KB
    __shared__ float mu[T], rs[T];

    {
        float* sf = &s[0][0];
        const float* gp = g_pool + bc * (T * FEAT);
        const float* pp = pos    + bc * (T * FEAT);
        for (int i = tid; i < T * FEAT; i += 256) sf[i] = gp[i] + pp[i];
    }
    __syncthreads();

    if (tid < T) {
        float m = 0.f, v = 0.f;
        #pragma unroll
        for (int f = 0; f < FEAT; f++) { float val = s[tid][f]; m += val; v += val * val; }
        m *= (1.f / FEAT);
        v = v * (1.f / FEAT) - m * m;
        mu[tid] = m;
        rs[tid] = rsqrtf(v + LN_EPS);
    }
    __syncthreads();
    {
        float* sf = &s[0][0];
        for (int i = tid; i < T * FEAT; i += 256) {
            int t = i >> 6, f = i & 63;
            sf[i] = (sf[i] - mu[t]) * rs[t] * gamma[f] + beta[f];
        }
    }
    __syncthreads();

    for (int i = tid; i < T * 2 * DH; i += 256) {
        const int t = i >> 7;
        const int o = i & 127;
        float acc = 0.f;
        #pragma unroll
        for (int f = 0; f < FEAT; f++) acc += s[t][f] * __ldg(&Wqk[f * (2 * DH) + o]);
        qk[t][o] = acc;
    }
    __syncthreads();

    {
        const int i = tid >> 4;
        const int j = tid & 15;
        float d = 0.f;
        #pragma unroll
        for (int k = 0; k < DH; k++) d += qk[i][k] * qk[j][DH + k];
        d *= 0.125f;                        // DH^-0.5

        float mx = d;
        #pragma unroll
        for (int m = 8; m; m >>= 1) mx = fmaxf(mx, __shfl_xor_sync(0xffffffffu, mx, m, 16));
        float e = __expf(d - mx);
        float ss = e;
        #pragma unroll
        for (int m = 8; m; m >>= 1) ss += __shfl_xor_sync(0xffffffffu, ss, m, 16);

        const float w = e / ss;
        unsigned long long wp;
        asm("mov.b64 %0, {%1, %1};" : "=l"(wp) : "f"(w));
        g_attn2[bc * (T * T) + i * T + j] = wp;   // [i][j] layout
    }
}

// ---------------------------------------------------------------------------
// K3: grid (7, CHUNK_B*C), block 224 (7*224 = 1568 = exact float2 cover).
// j-outer, accumulator-resident: acc[16] (32 regs), one x[j] (2 regs) live.
// Per (t,j): 1 broadcast LDS.64 + 1 FFMA2. x reads hit L2 (chunk from K1).
// out via streaming stores. ~48 regs -> no spills, ~6 CTAs/SM.
// ---------------------------------------------------------------------------
__global__ __launch_bounds__(224)
void out_kernel(const float* __restrict__ x, float* __restrict__ out, int bc0)
{
    const int bc  = bc0 + blockIdx.y;
    const int tid = threadIdx.x;

    __shared__ unsigned long long a2[T * T];   // 2 KB
    for (int i = tid; i < T * T; i += 224) a2[i] = g_attn2[bc * (T * T) + i];
    __syncthreads();

    const int b = bc >> 6;
    const int c = bc & 63;

    const unsigned long long* xb2 =
        reinterpret_cast<const unsigned long long*>(x);
    unsigned long long* ob2 = reinterpret_cast<unsigned long long*>(out);

    const int p2      = blockIdx.x * 224 + tid;   // [0, 1568)
    const int base2   = (b * T * C + c) * HW2;
    const int tstride = C * HW2;                  // per-t stride (float2)

    unsigned long long acc[T];
    #pragma unroll
    for (int t = 0; t < T; t++) acc[t] = 0ull;

    #pragma unroll
    for (int j = 0; j < T; j++) {
        const unsigned long long xj = __ldg(&xb2[base2 + j * tstride + p2]);
        #pragma unroll
        for (int t = 0; t < T; t++)
            acc[t] = ffma2(a2[t * T + j], xj, acc[t]);
        acc[j] = fadd2(acc[j], xj);               // residual
    }

    #pragma unroll
    for (int t = 0; t < T; t++)
        __stcs(&ob2[base2 + t * tstride + p2], acc[t]);
}

// ---------------------------------------------------------------------------
extern "C" void kernel_launch(void* const* d_in, const int* in_sizes, int n_in,
                              void* d_out, int out_size)
{
    const float* x     = (const float*)d_in[0];   // (8,16,64,56,56)
    const float* pos   = (const float*)d_in[1];   // (512,16,64)
    const float* Wqk   = (const float*)d_in[2];   // (64,128)
    const float* gamma = (const float*)d_in[3];   // (64,)
    const float* beta  = (const float*)d_in[4];   // (64,)
    float*       out   = (float*)d_out;

    // Chunked pipeline: 51.4 MB x-chunk stays L2-resident between its pool
    // pass and its output pass.
    for (int b0 = 0; b0 < B; b0 += CHUNK_B) {
        pool_kernel<<<CHUNK_B * T * C, 256>>>(x, b0 * T * C);
        attn_kernel<<<CHUNK_B * C, 256>>>(pos, Wqk, gamma, beta, b0 * C);
        out_kernel<<<dim3(7, CHUNK_B * C), 224>>>(x, out, b0 * C);
    }
}

// round 10
// speedup vs baseline: 1.5531x; 1.0282x over previous
#include <cuda_runtime.h>
#include <cuda_bf16.h>

// Fixed problem shapes
#define B    8
#define T    16
#define C    64
#define H    56
#define W_   56
#define HW   (H * W_)          // 3136
#define HW4  (HW / 4)          // 784  (float4 units)
#define HW2  (HW / 2)          // 1568 (float2 units)
#define DIM  8
#define POOL 7                 // H/DIM
#define FEAT (DIM * DIM)       // 64
#define DH   64                // dim_head
#define BC   (B * C)           // 512
#define LN_EPS 1e-5f

#define CHUNK_B 4              // batches per pipeline chunk (51.4 MB of x < 126 MB L2)

// Static device scratch (no allocations allowed)
__device__ float g_pool[BC * T * FEAT];   // 2 MB
__device__ float g_attn[BC * T * T];      // (bc,16,16) row-major, 512 KB

// ---------------------------------------------------------------------------
// K1: one CTA per (b,t,c) slice within the chunk. Stage 12.5 KB in smem,
// 7x7 mean-pool -> 64 cells, compile-time reduce offsets.
// ---------------------------------------------------------------------------
__global__ __launch_bounds__(256, 8)
void pool_kernel(const float* __restrict__ x, int slice0)
{
    const int slice = slice0 + blockIdx.x;   // ((b*T + t)*C + c)
    const int c = slice % C;
    const int t = (slice / C) % T;
    const int b = slice / (T * C);
    const int tid = threadIdx.x;

    __shared__ float stage[HW];              // 12544 B

    const float4* xs = reinterpret_cast<const float4*>(x) + (long)slice * HW4;
    float4* st4 = reinterpret_cast<float4*>(stage);
    // 784 = 3*256 + 16
    st4[tid]        = xs[tid];
    st4[tid + 256]  = xs[tid + 256];
    st4[tid + 512]  = xs[tid + 512];
    if (tid < 16) st4[tid + 768] = xs[tid + 768];
    __syncthreads();

    // 64 cells x 4 subs. sub handles rows {sub, sub+4} (sub==3: one row).
    const int cell = tid >> 2;
    const int sub  = tid & 3;
    const int ci   = cell >> 3;
    const int cj   = cell & 7;

    const float* r0 = stage + (ci * POOL + sub) * W_ + cj * POOL;
    float sum = 0.f;
    #pragma unroll
    for (int jj = 0; jj < POOL; jj++) sum += r0[jj];
    if (sub < 3) {
        #pragma unroll
        for (int jj = 0; jj < POOL; jj++) sum += r0[4 * W_ + jj];
    }
    sum += __shfl_xor_sync(0xffffffffu, sum, 1);
    sum += __shfl_xor_sync(0xffffffffu, sum, 2);
    if (sub == 0)
        g_pool[((b * C + c) * T + t) * FEAT + cell] = sum * (1.f / (POOL * POOL));
}

// ---------------------------------------------------------------------------
// K2: one CTA per (b,c) in chunk. +pos, LN, QK proj, dots, softmax ->
// g_attn (row-major floats). Tiny.
// ---------------------------------------------------------------------------
__global__ __launch_bounds__(256, 4)
void attn_kernel(const float* __restrict__ pos,
                 const float* __restrict__ Wqk,
                 const float* __restrict__ gamma,
                 const float* __restrict__ beta,
                 int bc0)
{
    const int bc  = bc0 + blockIdx.x;
    const int tid = threadIdx.x;

    __shared__ float s[T][FEAT];        // 4 KB
    __shared__ float qk[T][2 * DH];     // 8 KB
    __shared__ float mu[T], rs[T];

    {
        float* sf = &s[0][0];
        const float* gp = g_pool + bc * (T * FEAT);
        const float* pp = pos    + bc * (T * FEAT);
        for (int i = tid; i < T * FEAT; i += 256) sf[i] = gp[i] + pp[i];
    }
    __syncthreads();

    if (tid < T) {
        float m = 0.f, v = 0.f;
        #pragma unroll
        for (int f = 0; f < FEAT; f++) { float val = s[tid][f]; m += val; v += val * val; }
        m *= (1.f / FEAT);
        v = v * (1.f / FEAT) - m * m;
        mu[tid] = m;
        rs[tid] = rsqrtf(v + LN_EPS);
    }
    __syncthreads();
    {
        float* sf = &s[0][0];
        for (int i = tid; i < T * FEAT; i += 256) {
            int t = i >> 6, f = i & 63;
            sf[i] = (sf[i] - mu[t]) * rs[t] * gamma[f] + beta[f];
        }
    }
    __syncthreads();

    for (int i = tid; i < T * 2 * DH; i += 256) {
        const int t = i >> 7;
        const int o = i & 127;
        float acc = 0.f;
        #pragma unroll
        for (int f = 0; f < FEAT; f++) acc += s[t][f] * __ldg(&Wqk[f * (2 * DH) + o]);
        qk[t][o] = acc;
    }
    __syncthreads();

    {
        const int i = tid >> 4;
        const int j = tid & 15;
        float d = 0.f;
        #pragma unroll
        for (int k = 0; k < DH; k++) d += qk[i][k] * qk[j][DH + k];
        d *= 0.125f;                        // DH^-0.5

        float mx = d;
        #pragma unroll
        for (int m = 8; m; m >>= 1) mx = fmaxf(mx, __shfl_xor_sync(0xffffffffu, mx, m, 16));
        float e = __expf(d - mx);
        float ss = e;
        #pragma unroll
        for (int m = 8; m; m >>= 1) ss += __shfl_xor_sync(0xffffffffu, ss, m, 16);

        g_attn[bc * (T * T) + i * T + j] = e / ss;   // [i][j] row-major
    }
}

// ---------------------------------------------------------------------------
// K3: grid (7, CHUNK_B*C), block 224 (7*224 = 1568 = exact float2 cover).
// j-outer in chunks of 4, acc[16] float2 resident (32 regs). Weights fetched
// 4-at-a-time via broadcast LDS.128 (64 LDS total vs 256 in R9 -> crossbar
// off the critical path). Plain FFMA on components. x reads hit L2 (chunk
// streamed by K1); out via streaming stores. ~60 regs, no spills.
// ---------------------------------------------------------------------------
__global__ __launch_bounds__(224)
void out_kernel(const float* __restrict__ x, float* __restrict__ out, int bc0)
{
    const int bc  = bc0 + blockIdx.y;
    const int tid = threadIdx.x;

    __shared__ __align__(16) float a[T * T];   // 1 KB, row-major a[t][j]
    for (int i = tid; i < T * T; i += 224) a[i] = g_attn[bc * (T * T) + i];
    __syncthreads();

    const int b = bc >> 6;
    const int c = bc & 63;

    const float2* xb2 = reinterpret_cast<const float2*>(x);
    float2*       ob2 = reinterpret_cast<float2*>(out);

    const int p2      = blockIdx.x * 224 + tid;   // [0, 1568)
    const int base2   = (b * T * C + c) * HW2;
    const int tstride = C * HW2;                  // per-t stride (float2)

    float2 acc[T];
    #pragma unroll
    for (int t = 0; t < T; t++) acc[t] = make_float2(0.f, 0.f);

    #pragma unroll
    for (int jc = 0; jc < T; jc += 4) {
        // 4 x-loads for this j-chunk (independent, L2-hot)
        float2 xj0 = __ldg(&xb2[base2 + (jc + 0) * tstride + p2]);
        float2 xj1 = __ldg(&xb2[base2 + (jc + 1) * tstride + p2]);
        float2 xj2 = __ldg(&xb2[base2 + (jc + 2) * tstride + p2]);
        float2 xj3 = __ldg(&xb2[base2 + (jc + 3) * tstride + p2]);

        #pragma unroll
        for (int t = 0; t < T; t++) {
            const float4 w = *reinterpret_cast<const float4*>(&a[t * T + jc]);
            acc[t].x = fmaf(w.x, xj0.x, acc[t].x);
            acc[t].y = fmaf(w.x, xj0.y, acc[t].y);
            acc[t].x = fmaf(w.y, xj1.x, acc[t].x);
            acc[t].y = fmaf(w.y, xj1.y, acc[t].y);
            acc[t].x = fmaf(w.z, xj2.x, acc[t].x);
            acc[t].y = fmaf(w.z, xj2.y, acc[t].y);
            acc[t].x = fmaf(w.w, xj3.x, acc[t].x);
            acc[t].y = fmaf(w.w, xj3.y, acc[t].y);
        }
        // residuals for this chunk
        acc[jc + 0].x += xj0.x;  acc[jc + 0].y += xj0.y;
        acc[jc + 1].x += xj1.x;  acc[jc + 1].y += xj1.y;
        acc[jc + 2].x += xj2.x;  acc[jc + 2].y += xj2.y;
        acc[jc + 3].x += xj3.x;  acc[jc + 3].y += xj3.y;
    }

    #pragma unroll
    for (int t = 0; t < T; t++)
        __stcs(&ob2[base2 + t * tstride + p2], acc[t]);
}

// ---------------------------------------------------------------------------
extern "C" void kernel_launch(void* const* d_in, const int* in_sizes, int n_in,
                              void* d_out, int out_size)
{
    const float* x     = (const float*)d_in[0];   // (8,16,64,56,56)
    const float* pos   = (const float*)d_in[1];   // (512,16,64)
    const float* Wqk   = (const float*)d_in[2];   // (64,128)
    const float* gamma = (const float*)d_in[3];   // (64,)
    const float* beta  = (const float*)d_in[4];   // (64,)
    float*       out   = (float*)d_out;

    // Chunked pipeline: 51.4 MB x-chunk stays L2-resident between its pool
    // pass and its output pass.
    for (int b0 = 0; b0 < B; b0 += CHUNK_B) {
        pool_kernel<<<CHUNK_B * T * C, 256>>>(x, b0 * T * C);
        attn_kernel<<<CHUNK_B * C, 256>>>(pos, Wqk, gamma, beta, b0 * C);
        out_kernel<<<dim3(7, CHUNK_B * C), 224>>>(x, out, b0 * C);
    }
}

// round 11
// speedup vs baseline: 1.7175x; 1.1059x over previous
#include <cuda_runtime.h>
#include <cuda_bf16.h>

// Fixed problem shapes
#define B    8
#define T    16
#define C    64
#define H    56
#define W_   56
#define HW   (H * W_)          // 3136
#define HW4  (HW / 4)          // 784 (float4 units)
#define DIM  8
#define POOL 7                 // H/DIM
#define FEAT (DIM * DIM)       // 64
#define DH   64                // dim_head
#define BC   (B * C)           // 512
#define LN_EPS 1e-5f

#define THREADS 512
#define STAGE_BYTES (T * HW * 4)   // 200704 B of dynamic smem

typedef unsigned long long ull;

// Packed f32x2 ops (Blackwell)
__device__ __forceinline__ ull ffma2(ull a, ull b, ull c)
{
    ull d;
    asm("fma.rn.f32x2 %0, %1, %2, %3;" : "=l"(d) : "l"(a), "l"(b), "l"(c));
    return d;
}
__device__ __forceinline__ ull fadd2(ull a, ull b)
{
    ull d;
    asm("add.rn.f32x2 %0, %1, %2;" : "=l"(d) : "l"(a), "l"(b));
    return d;
}

union F4U { float4 f; ull u[2]; };

// ---------------------------------------------------------------------------
// Single fused kernel: one CTA per (b,c). The whole 196 KB x-slice lives in
// smem: x is read from DRAM exactly once, out written exactly once.
// ---------------------------------------------------------------------------
__global__ __launch_bounds__(THREADS, 1)
void fused_kernel(const float* __restrict__ x,
                  const float* __restrict__ pos,
                  const float* __restrict__ Wqk,
                  const float* __restrict__ gamma,
                  const float* __restrict__ beta,
                  float* __restrict__ out)
{
    extern __shared__ float stage[];             // [T][HW] = 196 KB
    __shared__ float s[T][FEAT];                 // 4 KB
    __shared__ float qk[T][2 * DH];              // 8 KB
    __shared__ float mu[T], rs[T];
    __shared__ __align__(16) ull a2[T * T];      // packed {w,w}, 2 KB

    const int bc  = blockIdx.x;
    const int b   = bc >> 6;
    const int c   = bc & 63;
    const int tid = threadIdx.x;

    // ---------------- load slice into smem (x read ONCE) ----------------
    const float4* xb  = reinterpret_cast<const float4*>(x);
    float4*       st4 = reinterpret_cast<float4*>(stage);
    const int base4 = (b * T * C + c) * HW4;     // (b, t=0, c) in float4
    const int tstr4 = C * HW4;                   // per-t stride (float4)

    #pragma unroll 4
    for (int i = tid; i < T * HW4; i += THREADS) {
        const int t = i / HW4;                   // const-div -> mul/shift
        const int p = i - t * HW4;
        st4[i] = __ldcs(&xb[base4 + t * tstr4 + p]);
    }
    __syncthreads();

    // ---------------- pooling: 1024 (t,cell) tasks ----------------
    for (int i = tid; i < T * FEAT; i += THREADS) {
        const int t    = i >> 6;
        const int cell = i & 63;
        const int ci   = cell >> 3;
        const int cj   = cell & 7;
        const float* r0 = stage + t * HW + (ci * POOL) * W_ + cj * POOL;
        float sum = 0.f;
        #pragma unroll
        for (int r = 0; r < POOL; r++)
            #pragma unroll
            for (int col = 0; col < POOL; col++)
                sum += r0[r * W_ + col];
        s[t][cell] = sum * (1.f / (POOL * POOL)) + pos[bc * (T * FEAT) + i];
    }
    __syncthreads();

    // ---------------- LayerNorm ----------------
    if (tid < T) {
        float m = 0.f, v = 0.f;
        #pragma unroll
        for (int f = 0; f < FEAT; f++) { float val = s[tid][f]; m += val; v += val * val; }
        m *= (1.f / FEAT);
        v = v * (1.f / FEAT) - m * m;
        mu[tid] = m;
        rs[tid] = rsqrtf(v + LN_EPS);
    }
    __syncthreads();
    for (int i = tid; i < T * FEAT; i += THREADS) {
        const int t = i >> 6, f = i & 63;
        s[t][f] = (s[t][f] - mu[t]) * rs[t] * gamma[f] + beta[f];
    }
    __syncthreads();

    // ---------------- qk = s @ Wqk : 2048 outputs, 4 per thread ----------------
    for (int i = tid; i < T * 2 * DH; i += THREADS) {
        const int t = i >> 7;
        const int o = i & 127;
        float acc = 0.f;
        #pragma unroll
        for (int f = 0; f < FEAT; f++) acc += s[t][f] * __ldg(&Wqk[f * (2 * DH) + o]);
        qk[t][o] = acc;
    }
    __syncthreads();

    // ---------------- dots + softmax -> packed a2 ----------------
    if (tid < T * T) {
        const int i = tid >> 4;
        const int j = tid & 15;
        float d = 0.f;
        #pragma unroll
        for (int k = 0; k < DH; k++) d += qk[i][k] * qk[j][DH + k];
        d *= 0.125f;                             // DH^-0.5

        float mx = d;
        #pragma unroll
        for (int m = 8; m; m >>= 1) mx = fmaxf(mx, __shfl_xor_sync(0xffffffffu, mx, m, 16));
        float e = __expf(d - mx);
        float ss = e;
        #pragma unroll
        for (int m = 8; m; m >>= 1) ss += __shfl_xor_sync(0xffffffffu, ss, m, 16);

        const float w = e / ss;
        ull wp;
        asm("mov.b64 %0, {%1, %1};" : "=l"(wp) : "f"(w));
        a2[i * T + j] = wp;                      // [i][j]
    }
    __syncthreads();

    // ---------------- out[t] = x[t] + sum_j a[t][j]*x[j] (from smem) --------
    float4* ob = reinterpret_cast<float4*>(out);

    for (int p4 = tid; p4 < HW4; p4 += THREADS) {
        // all 16 x[j] float4 register-resident (read from smem once)
        ull xv[T][2];
        #pragma unroll
        for (int j = 0; j < T; j++) {
            F4U v;
            v.f = *reinterpret_cast<const float4*>(stage + j * HW + 4 * p4);
            xv[j][0] = v.u[0];
            xv[j][1] = v.u[1];
        }

        #pragma unroll
        for (int t = 0; t < T; t++) {
            ull acc0 = xv[t][0];                 // residual
            ull acc1 = xv[t][1];
            #pragma unroll
            for (int jc = 0; jc < T; jc += 2) {
                // 2 packed weights per LDS.128 (broadcast)
                const ulonglong2 w =
                    *reinterpret_cast<const ulonglong2*>(&a2[t * T + jc]);
                acc0 = ffma2(w.x, xv[jc    ][0], acc0);
                acc1 = ffma2(w.x, xv[jc    ][1], acc1);
                acc0 = ffma2(w.y, xv[jc + 1][0], acc0);
                acc1 = ffma2(w.y, xv[jc + 1][1], acc1);
            }
            F4U r; r.u[0] = acc0; r.u[1] = acc1;
            __stcs(&ob[base4 + t * tstr4 + p4], r.f);
        }
    }
}

// ---------------------------------------------------------------------------
extern "C" void kernel_launch(void* const* d_in, const int* in_sizes, int n_in,
                              void* d_out, int out_size)
{
    const float* x     = (const float*)d_in[0];   // (8,16,64,56,56)
    const float* pos   = (const float*)d_in[1];   // (512,16,64)
    const float* Wqk   = (const float*)d_in[2];   // (64,128)
    const float* gamma = (const float*)d_in[3];   // (64,)
    const float* beta  = (const float*)d_in[4];   // (64,)
    float*       out   = (float*)d_out;

    // Opt in to 196 KB dynamic smem (idempotent, capture-safe: no stream work)
    cudaFuncSetAttribute(fused_kernel,
                         cudaFuncAttributeMaxDynamicSharedMemorySize,
                         STAGE_BYTES);

    fused_kernel<<<BC, THREADS, STAGE_BYTES>>>(x, pos, Wqk, gamma, beta, out);
}